// round 13
// baseline (speedup 1.0000x reference)
#include <cuda_runtime.h>
#include <cuda_fp16.h>
#include <math.h>

#define N_NODES 50000
#define N_EDGES 400000
#define N_GRAPHS 512
#define F 32
#define NB 32
#define CUTOFF 5.0f
#define FULL 0xffffffffu
#define TABK 4096                     // knots over t in [0,1]

// ---------------- device scratch (no allocations allowed) ----------------
__device__ float g_x0[N_NODES * F];              // x0, later x0'
__device__ float g_yacc[N_NODES * F];            // segment-sum accumulator
__device__ float g_t[N_EDGES];                   // per-edge t = r/cutoff (live edges)
__device__ unsigned char g_flag[N_EDGES];        // 1 = edge inside cutoff
__device__ float g_tab1[(TABK + 1) * F];         // p1(t) table
__device__ float g_tab2[(TABK + 1) * F];         // p2(t) table

__device__ __forceinline__ float siluf(float x) { return x * (1.f / (1.f + __expf(-x))); }

// ---------------- K0: x0 = embed[z], yacc = x0, zero d_out -------------------
__global__ void k_init(const float* __restrict__ embed, const int* __restrict__ z,
                       float* __restrict__ out) {
    int i = blockIdx.x * blockDim.x + threadIdx.x;
    if (i < N_GRAPHS) out[i] = 0.f;
    if (i < N_NODES * F) {
        int n = i >> 5, f = i & 31;
        float v = embed[z[n] * F + f];
        g_x0[i] = v;
        g_yacc[i] = v;
    }
}

// ---------------- KT: build p1/p2 tables (warp per knot) ---------------------
// p1[f](t) = sum_b rbf_b(r)·(Wy0+Wx0)[b][f],  p2[f](t) = sum_b rbf_b(r)·Wr[b][f]
__global__ void k_tab(const float* __restrict__ Wy0, const float* __restrict__ Wx0,
                      const float* __restrict__ Wr) {
    __shared__ float2 ws2[NB][F];
    for (int i = threadIdx.x; i < NB * F; i += blockDim.x) {
        int b = i >> 5, f = i & 31;
        ws2[b][f] = make_float2(__ldg(&Wy0[i]) + __ldg(&Wx0[i]), __ldg(&Wr[i]));
    }
    __syncthreads();
    int lane = threadIdx.x & 31;
    int k    = blockIdx.x * (blockDim.x >> 5) + (threadIdx.x >> 5);
    if (k > TABK) return;

    float t = (float)k * (1.f / (float)TABK);
    float rbf = 0.f;
    if (t < 1.f) {
        float r = t * CUTOFF;
        float lb = lgammaf((float)NB) - lgammaf((float)lane + 1.f)
                 - lgammaf((float)NB - (float)lane);
        float kf = (float)lane;
        float fc = __expf(1.f - __fdividef(1.f, fmaxf(1.f - t * t, 1e-7f)));
        float u = __fdividef(r, r + 1.f);
        u = fminf(fmaxf(u, 1e-7f), 1.f - 1e-7f);
        rbf = __expf(lb + kf * __logf(u) + ((float)NB - 1.f - kf) * __logf(1.f - u)) * fc;
    }
    float p1 = 0.f, p2 = 0.f;
#pragma unroll
    for (int b = 0; b < NB; b++) {
        float rb = __shfl_sync(FULL, rbf, b);
        float2 w = ws2[b][lane];
        p1 = fmaf(rb, w.x, p1);
        p2 = fmaf(rb, w.y, p2);
    }
    g_tab1[k * F + lane] = p1;
    g_tab2[k * F + lane] = p2;
}

// ---------------- K1: edge pass 1 — table lookup, no matvec ------------------
__global__ void k_edge1(const float* __restrict__ pos,
                        const int* __restrict__ src, const int* __restrict__ dst) {
    int lane   = threadIdx.x & 31;
    int warp   = blockIdx.x * (blockDim.x >> 5) + (threadIdx.x >> 5);
    int nwarps = gridDim.x * (blockDim.x >> 5);

    for (int e = warp; e < N_EDGES; e += nwarps) {
        int s = __ldg(&src[e]);
        int d = __ldg(&dst[e]);
        float dx = __ldg(&pos[s * 3 + 0]) - __ldg(&pos[d * 3 + 0]);
        float dy = __ldg(&pos[s * 3 + 1]) - __ldg(&pos[d * 3 + 1]);
        float dz = __ldg(&pos[s * 3 + 2]) - __ldg(&pos[d * 3 + 2]);
        float r = sqrtf(dx * dx + dy * dy + dz * dz + 1e-12f);
        float t = r * (1.f / CUTOFF);

        if (t >= 1.f) {
            if (lane == 0) g_flag[e] = 0;
            continue;
        }
        if (lane == 0) { g_flag[e] = 1; g_t[e] = t; }
        float ft = t * (float)TABK;
        int   i0 = (int)ft;
        float fr = ft - (float)i0;
        float a = __ldg(&g_tab1[i0 * F + lane]);
        float b = __ldg(&g_tab1[i0 * F + F + lane]);
        float p1 = fmaf(fr, b - a, a);
        float msg = p1 * __ldg(&g_x0[s * F + lane]);
        atomicAdd(&g_yacc[d * F + lane], msg);
    }
}

// ---------------- K2: node update 1 (dense->silu->dense, residual) -----------
__global__ void k_node1(const float* __restrict__ W1, const float* __restrict__ b1,
                        const float* __restrict__ W2, const float* __restrict__ b2,
                        const float* __restrict__ c0) {
    __shared__ float W1s[F][F];
    __shared__ float W2s[F][F];
    for (int i = threadIdx.x; i < F * F; i += blockDim.x) {
        W1s[i >> 5][i & 31] = __ldg(&W1[i]);
        W2s[i >> 5][i & 31] = __ldg(&W2[i]);
    }
    __syncthreads();
    int lane   = threadIdx.x & 31;
    int warp   = blockIdx.x * (blockDim.x >> 5) + (threadIdx.x >> 5);
    int nwarps = gridDim.x * (blockDim.x >> 5);
    float sc  = siluf(__ldg(&c0[0]));
    float bb1 = __ldg(&b1[lane]), bb2 = __ldg(&b2[lane]);

    for (int n = warp; n < N_NODES; n += nwarps) {
        float y = g_yacc[n * F + lane];
        float y1 = bb1;
#pragma unroll
        for (int f = 0; f < F; f++) y1 = fmaf(__shfl_sync(FULL, y, f), W1s[f][lane], y1);
        float g = siluf(y1);
        float y2 = bb2;
#pragma unroll
        for (int f = 0; f < F; f++) y2 = fmaf(__shfl_sync(FULL, g, f), W2s[f][lane], y2);
        float xp = g_x0[n * F + lane] + sc * y2;
        g_x0[n * F + lane]   = xp;     // x0' for pass 2
        g_yacc[n * F + lane] = xp;     // init accumulator for y0
    }
}

// ---------------- K3: edge pass 2 — 8 edges/warp, float4, p2 from table ------
__global__ void k_edge2(const int* __restrict__ src, const int* __restrict__ dst) {
    int lane   = threadIdx.x & 31;
    int g      = lane >> 3;          // edge subgroup 0..3
    int j      = lane & 7;           // feature group (4 floats each)
    int warp   = blockIdx.x * (blockDim.x >> 5) + (threadIdx.x >> 5);
    int nwarps = gridDim.x * (blockDim.x >> 5);
    const float4* tab2v = reinterpret_cast<const float4*>(g_tab2);

    for (int e0 = warp * 8; e0 < N_EDGES; e0 += nwarps * 8) {
        unsigned long long fl8 = *reinterpret_cast<const unsigned long long*>(&g_flag[e0]);
        if (!fl8) continue;                                   // all 8 dead
        int sd = 0;
        float tl = 0.f;
        if (lane < 16) sd = __ldg(lane < 8 ? &src[e0 + lane] : &dst[e0 + (lane - 8)]);
        if (lane < 8)  tl = g_t[e0 + lane];
        int sA = __shfl_sync(FULL, sd, g);
        int dA = __shfl_sync(FULL, sd, 8 + g);
        int sB = __shfl_sync(FULL, sd, 4 + g);
        int dB = __shfl_sync(FULL, sd, 12 + g);
        float tA = __shfl_sync(FULL, tl, g);
        float tB = __shfl_sync(FULL, tl, 4 + g);
        bool fA = (fl8 >> (8 * g)) & 0xff;
        bool fB = (fl8 >> (8 * (4 + g))) & 0xff;

        float4 mA, mB;                 // issue both gather chains before both REDs
        if (fA) {
            float ft = tA * (float)TABK;
            int   i0 = (int)ft;
            float fr = ft - (float)i0;
            float4 a = tab2v[i0 * 8 + j];
            float4 b = tab2v[i0 * 8 + 8 + j];
            float4 xv = *reinterpret_cast<const float4*>(&g_x0[(size_t)sA * F + j * 4]);
            mA = make_float4(fmaf(fr, b.x - a.x, a.x) * xv.x,
                             fmaf(fr, b.y - a.y, a.y) * xv.y,
                             fmaf(fr, b.z - a.z, a.z) * xv.z,
                             fmaf(fr, b.w - a.w, a.w) * xv.w);
        }
        if (fB) {
            float ft = tB * (float)TABK;
            int   i0 = (int)ft;
            float fr = ft - (float)i0;
            float4 a = tab2v[i0 * 8 + j];
            float4 b = tab2v[i0 * 8 + 8 + j];
            float4 xv = *reinterpret_cast<const float4*>(&g_x0[(size_t)sB * F + j * 4]);
            mB = make_float4(fmaf(fr, b.x - a.x, a.x) * xv.x,
                             fmaf(fr, b.y - a.y, a.y) * xv.y,
                             fmaf(fr, b.z - a.z, a.z) * xv.z,
                             fmaf(fr, b.w - a.w, a.w) * xv.w);
        }
        if (fA) atomicAdd(reinterpret_cast<float4*>(&g_yacc[(size_t)dA * F + j * 4]), mA);
        if (fB) atomicAdd(reinterpret_cast<float4*>(&g_yacc[(size_t)dB * F + j * 4]), mB);
    }
}

// ---------------- K4: node update 2 + readout, scatter straight to d_out -----
__global__ void k_node2(const float* __restrict__ W11, const float* __restrict__ b11,
                        const float* __restrict__ W21, const float* __restrict__ b21,
                        const float* __restrict__ c1,
                        const float* __restrict__ Wro1, const float* __restrict__ bro1,
                        const float* __restrict__ Wro2, const float* __restrict__ bro2,
                        const float* __restrict__ abias, const int* __restrict__ z,
                        const int* __restrict__ bseg, float* __restrict__ out) {
    __shared__ float W11s[F][F];
    __shared__ float W21s[F][F];
    __shared__ float Wro1s[F][F];
    for (int i = threadIdx.x; i < F * F; i += blockDim.x) {
        W11s[i >> 5][i & 31]  = __ldg(&W11[i]);
        W21s[i >> 5][i & 31]  = __ldg(&W21[i]);
        Wro1s[i >> 5][i & 31] = __ldg(&Wro1[i]);
    }
    __syncthreads();
    int lane   = threadIdx.x & 31;
    int warp   = blockIdx.x * (blockDim.x >> 5) + (threadIdx.x >> 5);
    int nwarps = gridDim.x * (blockDim.x >> 5);
    float sc   = siluf(__ldg(&c1[0]));
    float w2c  = __ldg(&Wro2[lane]);
    float bb11 = __ldg(&b11[lane]), bb21 = __ldg(&b21[lane]), bbr = __ldg(&bro1[lane]);
    float br2  = __ldg(&bro2[0]);

    for (int n = warp; n < N_NODES; n += nwarps) {
        float y0 = g_yacc[n * F + lane];
        float a = bb11;
#pragma unroll
        for (int f = 0; f < F; f++) a = fmaf(__shfl_sync(FULL, y0, f), W11s[f][lane], a);
        a = siluf(a);
        float yb = bb21;
#pragma unroll
        for (int f = 0; f < F; f++) yb = fmaf(__shfl_sync(FULL, a, f), W21s[f][lane], yb);
        float xs0 = g_x0[n * F + lane] + sc * yb;
        float h = bbr;
#pragma unroll
        for (int f = 0; f < F; f++) h = fmaf(__shfl_sync(FULL, xs0, f), Wro1s[f][lane], h);
        h = siluf(h);
        float part = h * w2c;
#pragma unroll
        for (int off = 16; off; off >>= 1) part += __shfl_xor_sync(FULL, part, off);
        if (lane == 0) {
            float ea = part + br2 + __ldg(&abias[z[n]]);
            atomicAdd(&out[bseg[n]], ea);
        }
    }
}

// ---------------- launch ------------------------------------------------------
extern "C" void kernel_launch(void* const* d_in, const int* in_sizes, int n_in,
                              void* d_out, int out_size) {
    const float* positions  = (const float*)d_in[0];
    const float* embed      = (const float*)d_in[1];
    const float* Wy0        = (const float*)d_in[2];
    const float* Wx0        = (const float*)d_in[3];
    const float* W1_0       = (const float*)d_in[4];
    const float* b1_0       = (const float*)d_in[5];
    const float* W2_0       = (const float*)d_in[6];
    const float* b2_0       = (const float*)d_in[7];
    const float* c0         = (const float*)d_in[8];
    const float* Wr_last    = (const float*)d_in[9];
    const float* W1_1       = (const float*)d_in[10];
    const float* b1_1       = (const float*)d_in[11];
    const float* W2_1       = (const float*)d_in[12];
    const float* b2_1       = (const float*)d_in[13];
    const float* c1         = (const float*)d_in[14];
    const float* Wro1       = (const float*)d_in[15];
    const float* bro1       = (const float*)d_in[16];
    const float* Wro2       = (const float*)d_in[17];
    const float* bro2       = (const float*)d_in[18];
    const float* abias      = (const float*)d_in[19];
    const int*   z          = (const int*)d_in[20];
    const int*   dst_idx    = (const int*)d_in[21];
    const int*   src_idx    = (const int*)d_in[22];
    const int*   bseg       = (const int*)d_in[23];
    float*       out        = (float*)d_out;

    k_init<<<(N_NODES * F + 255) / 256, 256>>>(embed, z, out);
    k_tab<<<(TABK + 1 + 7) / 8, 256>>>(Wy0, Wx0, Wr_last);
    k_edge1<<<2048, 256>>>(positions, src_idx, dst_idx);
    k_node1<<<1024, 256>>>(W1_0, b1_0, W2_0, b2_0, c0);
    k_edge2<<<2048, 256>>>(src_idx, dst_idx);
    k_node2<<<1024, 256>>>(W1_1, b1_1, W2_1, b2_1, c1,
                           Wro1, bro1, Wro2, bro2, abias, z, bseg, out);
}

// round 15
// speedup vs baseline: 1.9956x; 1.9956x over previous
#include <cuda_runtime.h>
#include <cuda_fp16.h>
#include <math.h>

#define N_NODES 50000
#define N_EDGES 400000
#define N_GRAPHS 512
#define F 32
#define NB 32
#define CUTOFF 5.0f
#define FULL 0xffffffffu
#define TABK 4096                     // knots over t in [0,1]

// ---------------- device scratch (no allocations allowed) ----------------
__device__ float g_x0[N_NODES * F];              // x0, later x0'
__device__ float g_yacc[N_NODES * F];            // segment-sum accumulator
__device__ float g_t[N_EDGES];                   // per-edge t = r/cutoff (all edges)
__device__ float g_tab1[(TABK + 1) * F];         // p1(t) table
__device__ float g_tab2[(TABK + 1) * F];         // p2(t) table

__device__ __forceinline__ float siluf(float x) { return x * (1.f / (1.f + __expf(-x))); }

// ---------------- K0: x0 = embed[z], yacc = x0, zero d_out -------------------
__global__ void k_init(const float* __restrict__ embed, const int* __restrict__ z,
                       float* __restrict__ out) {
    int i = blockIdx.x * blockDim.x + threadIdx.x;
    if (i < N_GRAPHS) out[i] = 0.f;
    if (i < N_NODES * F) {
        int n = i >> 5, f = i & 31;
        float v = embed[z[n] * F + f];
        g_x0[i] = v;
        g_yacc[i] = v;
    }
}

// ---------------- KT: build p1/p2 tables (warp per knot) ---------------------
__global__ void k_tab(const float* __restrict__ Wy0, const float* __restrict__ Wx0,
                      const float* __restrict__ Wr) {
    __shared__ float2 ws2[NB][F];
    for (int i = threadIdx.x; i < NB * F; i += blockDim.x) {
        int b = i >> 5, f = i & 31;
        ws2[b][f] = make_float2(__ldg(&Wy0[i]) + __ldg(&Wx0[i]), __ldg(&Wr[i]));
    }
    __syncthreads();
    int lane = threadIdx.x & 31;
    int k    = blockIdx.x * (blockDim.x >> 5) + (threadIdx.x >> 5);
    if (k > TABK) return;

    float t = (float)k * (1.f / (float)TABK);
    float rbf = 0.f;
    if (t < 1.f) {
        float r = t * CUTOFF;
        float lb = lgammaf((float)NB) - lgammaf((float)lane + 1.f)
                 - lgammaf((float)NB - (float)lane);
        float kf = (float)lane;
        float fc = __expf(1.f - __fdividef(1.f, fmaxf(1.f - t * t, 1e-7f)));
        float u = __fdividef(r, r + 1.f);
        u = fminf(fmaxf(u, 1e-7f), 1.f - 1e-7f);
        rbf = __expf(lb + kf * __logf(u) + ((float)NB - 1.f - kf) * __logf(1.f - u)) * fc;
    }
    float p1 = 0.f, p2 = 0.f;
#pragma unroll
    for (int b = 0; b < NB; b++) {
        float rb = __shfl_sync(FULL, rbf, b);
        float2 w = ws2[b][lane];
        p1 = fmaf(rb, w.x, p1);
        p2 = fmaf(rb, w.y, p2);
    }
    g_tab1[k * F + lane] = p1;
    g_tab2[k * F + lane] = p2;
}

// ---------------- K1: edge pass 1 — 8 edges/warp, geometry on lanes 0..7 -----
__global__ void k_edge1(const float* __restrict__ pos,
                        const int* __restrict__ src, const int* __restrict__ dst) {
    int lane   = threadIdx.x & 31;
    int g      = lane >> 3;          // edge subgroup 0..3
    int j      = lane & 7;           // feature group (4 floats each)
    int warp   = blockIdx.x * (blockDim.x >> 5) + (threadIdx.x >> 5);
    int nwarps = gridDim.x * (blockDim.x >> 5);
    const float4* tab1v = reinterpret_cast<const float4*>(g_tab1);

    for (int e0 = warp * 8; e0 < N_EDGES; e0 += nwarps * 8) {
        int s = 0, d = 0;
        float t = 2.f;
        if (lane < 8) {                        // one edge's geometry per lane
            s = __ldg(&src[e0 + lane]);
            d = __ldg(&dst[e0 + lane]);
            float ax = __ldg(&pos[s * 3 + 0]);
            float ay = __ldg(&pos[s * 3 + 1]);
            float az = __ldg(&pos[s * 3 + 2]);
            float bx = __ldg(&pos[d * 3 + 0]);
            float by = __ldg(&pos[d * 3 + 1]);
            float bz = __ldg(&pos[d * 3 + 2]);
            float dx = ax - bx, dy = ay - by, dz = az - bz;
            float r = sqrtf(dx * dx + dy * dy + dz * dz + 1e-12f);
            t = r * (1.f / CUTOFF);
            g_t[e0 + lane] = t;                // always written (deterministic)
        }
        int   sA = __shfl_sync(FULL, s, g);
        int   dA = __shfl_sync(FULL, d, g);
        int   sB = __shfl_sync(FULL, s, 4 + g);
        int   dB = __shfl_sync(FULL, d, 4 + g);
        float tA = __shfl_sync(FULL, t, g);
        float tB = __shfl_sync(FULL, t, 4 + g);
        bool fA = (tA < 1.f), fB = (tB < 1.f);

        float4 mA, mB;                 // both gather chains in flight before REDs
        if (fA) {
            float ft = tA * (float)TABK;
            int   i0 = (int)ft;
            float fr = ft - (float)i0;
            float4 a = tab1v[i0 * 8 + j];
            float4 b = tab1v[i0 * 8 + 8 + j];
            float4 xv = *reinterpret_cast<const float4*>(&g_x0[(size_t)sA * F + j * 4]);
            mA = make_float4(fmaf(fr, b.x - a.x, a.x) * xv.x,
                             fmaf(fr, b.y - a.y, a.y) * xv.y,
                             fmaf(fr, b.z - a.z, a.z) * xv.z,
                             fmaf(fr, b.w - a.w, a.w) * xv.w);
        }
        if (fB) {
            float ft = tB * (float)TABK;
            int   i0 = (int)ft;
            float fr = ft - (float)i0;
            float4 a = tab1v[i0 * 8 + j];
            float4 b = tab1v[i0 * 8 + 8 + j];
            float4 xv = *reinterpret_cast<const float4*>(&g_x0[(size_t)sB * F + j * 4]);
            mB = make_float4(fmaf(fr, b.x - a.x, a.x) * xv.x,
                             fmaf(fr, b.y - a.y, a.y) * xv.y,
                             fmaf(fr, b.z - a.z, a.z) * xv.z,
                             fmaf(fr, b.w - a.w, a.w) * xv.w);
        }
        if (fA) atomicAdd(reinterpret_cast<float4*>(&g_yacc[(size_t)dA * F + j * 4]), mA);
        if (fB) atomicAdd(reinterpret_cast<float4*>(&g_yacc[(size_t)dB * F + j * 4]), mB);
    }
}

// ---------------- K2: node update 1 (dense->silu->dense, residual) -----------
__global__ void k_node1(const float* __restrict__ W1, const float* __restrict__ b1,
                        const float* __restrict__ W2, const float* __restrict__ b2,
                        const float* __restrict__ c0) {
    __shared__ float W1s[F][F];
    __shared__ float W2s[F][F];
    for (int i = threadIdx.x; i < F * F; i += blockDim.x) {
        W1s[i >> 5][i & 31] = __ldg(&W1[i]);
        W2s[i >> 5][i & 31] = __ldg(&W2[i]);
    }
    __syncthreads();
    int lane   = threadIdx.x & 31;
    int warp   = blockIdx.x * (blockDim.x >> 5) + (threadIdx.x >> 5);
    int nwarps = gridDim.x * (blockDim.x >> 5);
    float sc  = siluf(__ldg(&c0[0]));
    float bb1 = __ldg(&b1[lane]), bb2 = __ldg(&b2[lane]);

    for (int n = warp; n < N_NODES; n += nwarps) {
        float y = g_yacc[n * F + lane];
        float y1 = bb1;
#pragma unroll
        for (int f = 0; f < F; f++) y1 = fmaf(__shfl_sync(FULL, y, f), W1s[f][lane], y1);
        float g = siluf(y1);
        float y2 = bb2;
#pragma unroll
        for (int f = 0; f < F; f++) y2 = fmaf(__shfl_sync(FULL, g, f), W2s[f][lane], y2);
        float xp = g_x0[n * F + lane] + sc * y2;
        g_x0[n * F + lane]   = xp;     // x0' for pass 2
        g_yacc[n * F + lane] = xp;     // init accumulator for y0
    }
}

// ---------------- K3: edge pass 2 — 8 edges/warp, float4, p2 from table ------
__global__ void k_edge2(const int* __restrict__ src, const int* __restrict__ dst) {
    int lane   = threadIdx.x & 31;
    int g      = lane >> 3;
    int j      = lane & 7;
    int warp   = blockIdx.x * (blockDim.x >> 5) + (threadIdx.x >> 5);
    int nwarps = gridDim.x * (blockDim.x >> 5);
    const float4* tab2v = reinterpret_cast<const float4*>(g_tab2);

    for (int e0 = warp * 8; e0 < N_EDGES; e0 += nwarps * 8) {
        int sd = 0;
        float tl = 2.f;
        if (lane < 16) sd = __ldg(lane < 8 ? &src[e0 + lane] : &dst[e0 + (lane - 8)]);
        if (lane < 8)  tl = g_t[e0 + lane];
        int   sA = __shfl_sync(FULL, sd, g);
        int   dA = __shfl_sync(FULL, sd, 8 + g);
        int   sB = __shfl_sync(FULL, sd, 4 + g);
        int   dB = __shfl_sync(FULL, sd, 12 + g);
        float tA = __shfl_sync(FULL, tl, g);
        float tB = __shfl_sync(FULL, tl, 4 + g);
        bool fA = (tA < 1.f), fB = (tB < 1.f);

        float4 mA, mB;
        if (fA) {
            float ft = tA * (float)TABK;
            int   i0 = (int)ft;
            float fr = ft - (float)i0;
            float4 a = tab2v[i0 * 8 + j];
            float4 b = tab2v[i0 * 8 + 8 + j];
            float4 xv = *reinterpret_cast<const float4*>(&g_x0[(size_t)sA * F + j * 4]);
            mA = make_float4(fmaf(fr, b.x - a.x, a.x) * xv.x,
                             fmaf(fr, b.y - a.y, a.y) * xv.y,
                             fmaf(fr, b.z - a.z, a.z) * xv.z,
                             fmaf(fr, b.w - a.w, a.w) * xv.w);
        }
        if (fB) {
            float ft = tB * (float)TABK;
            int   i0 = (int)ft;
            float fr = ft - (float)i0;
            float4 a = tab2v[i0 * 8 + j];
            float4 b = tab2v[i0 * 8 + 8 + j];
            float4 xv = *reinterpret_cast<const float4*>(&g_x0[(size_t)sB * F + j * 4]);
            mB = make_float4(fmaf(fr, b.x - a.x, a.x) * xv.x,
                             fmaf(fr, b.y - a.y, a.y) * xv.y,
                             fmaf(fr, b.z - a.z, a.z) * xv.z,
                             fmaf(fr, b.w - a.w, a.w) * xv.w);
        }
        if (fA) atomicAdd(reinterpret_cast<float4*>(&g_yacc[(size_t)dA * F + j * 4]), mA);
        if (fB) atomicAdd(reinterpret_cast<float4*>(&g_yacc[(size_t)dB * F + j * 4]), mB);
    }
}

// ---------------- K4: node update 2 + readout, scatter straight to d_out -----
__global__ void k_node2(const float* __restrict__ W11, const float* __restrict__ b11,
                        const float* __restrict__ W21, const float* __restrict__ b21,
                        const float* __restrict__ c1,
                        const float* __restrict__ Wro1, const float* __restrict__ bro1,
                        const float* __restrict__ Wro2, const float* __restrict__ bro2,
                        const float* __restrict__ abias, const int* __restrict__ z,
                        const int* __restrict__ bseg, float* __restrict__ out) {
    __shared__ float W11s[F][F];
    __shared__ float W21s[F][F];
    __shared__ float Wro1s[F][F];
    for (int i = threadIdx.x; i < F * F; i += blockDim.x) {
        W11s[i >> 5][i & 31]  = __ldg(&W11[i]);
        W21s[i >> 5][i & 31]  = __ldg(&W21[i]);
        Wro1s[i >> 5][i & 31] = __ldg(&Wro1[i]);
    }
    __syncthreads();
    int lane   = threadIdx.x & 31;
    int warp   = blockIdx.x * (blockDim.x >> 5) + (threadIdx.x >> 5);
    int nwarps = gridDim.x * (blockDim.x >> 5);
    float sc   = siluf(__ldg(&c1[0]));
    float w2c  = __ldg(&Wro2[lane]);
    float bb11 = __ldg(&b11[lane]), bb21 = __ldg(&b21[lane]), bbr = __ldg(&bro1[lane]);
    float br2  = __ldg(&bro2[0]);

    for (int n = warp; n < N_NODES; n += nwarps) {
        float y0 = g_yacc[n * F + lane];
        float a = bb11;
#pragma unroll
        for (int f = 0; f < F; f++) a = fmaf(__shfl_sync(FULL, y0, f), W11s[f][lane], a);
        a = siluf(a);
        float yb = bb21;
#pragma unroll
        for (int f = 0; f < F; f++) yb = fmaf(__shfl_sync(FULL, a, f), W21s[f][lane], yb);
        float xs0 = g_x0[n * F + lane] + sc * yb;
        float h = bbr;
#pragma unroll
        for (int f = 0; f < F; f++) h = fmaf(__shfl_sync(FULL, xs0, f), Wro1s[f][lane], h);
        h = siluf(h);
        float part = h * w2c;
#pragma unroll
        for (int off = 16; off; off >>= 1) part += __shfl_xor_sync(FULL, part, off);
        if (lane == 0) {
            float ea = part + br2 + __ldg(&abias[z[n]]);
            atomicAdd(&out[bseg[n]], ea);
        }
    }
}

// ---------------- launch ------------------------------------------------------
extern "C" void kernel_launch(void* const* d_in, const int* in_sizes, int n_in,
                              void* d_out, int out_size) {
    const float* positions  = (const float*)d_in[0];
    const float* embed      = (const float*)d_in[1];
    const float* Wy0        = (const float*)d_in[2];
    const float* Wx0        = (const float*)d_in[3];
    const float* W1_0       = (const float*)d_in[4];
    const float* b1_0       = (const float*)d_in[5];
    const float* W2_0       = (const float*)d_in[6];
    const float* b2_0       = (const float*)d_in[7];
    const float* c0         = (const float*)d_in[8];
    const float* Wr_last    = (const float*)d_in[9];
    const float* W1_1       = (const float*)d_in[10];
    const float* b1_1       = (const float*)d_in[11];
    const float* W2_1       = (const float*)d_in[12];
    const float* b2_1       = (const float*)d_in[13];
    const float* c1         = (const float*)d_in[14];
    const float* Wro1       = (const float*)d_in[15];
    const float* bro1       = (const float*)d_in[16];
    const float* Wro2       = (const float*)d_in[17];
    const float* bro2       = (const float*)d_in[18];
    const float* abias      = (const float*)d_in[19];
    const int*   z          = (const int*)d_in[20];
    const int*   dst_idx    = (const int*)d_in[21];
    const int*   src_idx    = (const int*)d_in[22];
    const int*   bseg       = (const int*)d_in[23];
    float*       out        = (float*)d_out;

    k_init<<<(N_NODES * F + 255) / 256, 256>>>(embed, z, out);
    k_tab<<<(TABK + 1 + 7) / 8, 256>>>(Wy0, Wx0, Wr_last);
    k_edge1<<<2048, 256>>>(positions, src_idx, dst_idx);
    k_node1<<<1024, 256>>>(W1_0, b1_0, W2_0, b2_0, c0);
    k_edge2<<<2048, 256>>>(src_idx, dst_idx);
    k_node2<<<1024, 256>>>(W1_1, b1_1, W2_1, b2_1, c1,
                           Wro1, bro1, Wro2, bro2, abias, z, bseg, out);
}

// round 16
// speedup vs baseline: 2.6220x; 1.3139x over previous
#include <cuda_runtime.h>
#include <cuda_fp16.h>
#include <math.h>

#define N_NODES 50000
#define N_EDGES 400000
#define N_GRAPHS 512
#define F 32
#define NB 32
#define CUTOFF 5.0f
#define FULL 0xffffffffu
#define TABK 4096                     // knots over t in [0,1]

// ---------------- device scratch (no allocations allowed) ----------------
__device__ float g_x0[N_NODES * F];              // x0, later x0'
__device__ float g_yacc[N_NODES * F];            // segment-sum accumulator
__device__ float g_t[N_EDGES];                   // per-edge t = r/cutoff (all edges)
__device__ float g_tab1[(TABK + 1) * F];         // p1(t) table
__device__ float g_tab2[(TABK + 1) * F];         // p2(t) table

__device__ __forceinline__ float siluf(float x) { return x * (1.f / (1.f + __expf(-x))); }

typedef unsigned long long ull;
__device__ __forceinline__ ull pk2(float a, float b) {
    ull r; asm("mov.b64 %0, {%1, %2};" : "=l"(r) : "f"(a), "f"(b)); return r;
}
__device__ __forceinline__ void upk2(ull v, float& a, float& b) {
    asm("mov.b64 {%0, %1}, %2;" : "=f"(a), "=f"(b) : "l"(v));
}
__device__ __forceinline__ void fma2(ull& acc, ull a, ull b) {
    asm("fma.rn.f32x2 %0, %1, %2, %0;" : "+l"(acc) : "l"(a), "l"(b));
}

// ---------------- K0: x0 = embed[z], yacc = x0, zero d_out -------------------
__global__ void k_init(const float* __restrict__ embed, const int* __restrict__ z,
                       float* __restrict__ out) {
    int i = blockIdx.x * blockDim.x + threadIdx.x;
    if (i < N_GRAPHS) out[i] = 0.f;
    if (i < N_NODES * F) {
        int n = i >> 5, f = i & 31;
        float v = embed[z[n] * F + f];
        g_x0[i] = v;
        g_yacc[i] = v;
    }
}

// ---------------- KT: build p1/p2 tables (warp per knot) ---------------------
__global__ void k_tab(const float* __restrict__ Wy0, const float* __restrict__ Wx0,
                      const float* __restrict__ Wr) {
    __shared__ float2 ws2[NB][F];
    for (int i = threadIdx.x; i < NB * F; i += blockDim.x) {
        int b = i >> 5, f = i & 31;
        ws2[b][f] = make_float2(__ldg(&Wy0[i]) + __ldg(&Wx0[i]), __ldg(&Wr[i]));
    }
    __syncthreads();
    int lane = threadIdx.x & 31;
    int k    = blockIdx.x * (blockDim.x >> 5) + (threadIdx.x >> 5);
    if (k > TABK) return;

    float t = (float)k * (1.f / (float)TABK);
    float rbf = 0.f;
    if (t < 1.f) {
        float r = t * CUTOFF;
        float lb = lgammaf((float)NB) - lgammaf((float)lane + 1.f)
                 - lgammaf((float)NB - (float)lane);
        float kf = (float)lane;
        float fc = __expf(1.f - __fdividef(1.f, fmaxf(1.f - t * t, 1e-7f)));
        float u = __fdividef(r, r + 1.f);
        u = fminf(fmaxf(u, 1e-7f), 1.f - 1e-7f);
        rbf = __expf(lb + kf * __logf(u) + ((float)NB - 1.f - kf) * __logf(1.f - u)) * fc;
    }
    float p1 = 0.f, p2 = 0.f;
#pragma unroll
    for (int b = 0; b < NB; b++) {
        float rb = __shfl_sync(FULL, rbf, b);
        float2 w = ws2[b][lane];
        p1 = fmaf(rb, w.x, p1);
        p2 = fmaf(rb, w.y, p2);
    }
    g_tab1[k * F + lane] = p1;
    g_tab2[k * F + lane] = p2;
}

// ---------------- K1: edge pass 1 — 8 edges/warp, geometry on lanes 0..7 -----
__global__ void k_edge1(const float* __restrict__ pos,
                        const int* __restrict__ src, const int* __restrict__ dst) {
    int lane   = threadIdx.x & 31;
    int g      = lane >> 3;          // edge subgroup 0..3
    int j      = lane & 7;           // feature group (4 floats each)
    int warp   = blockIdx.x * (blockDim.x >> 5) + (threadIdx.x >> 5);
    int nwarps = gridDim.x * (blockDim.x >> 5);
    const float4* tab1v = reinterpret_cast<const float4*>(g_tab1);

    for (int e0 = warp * 8; e0 < N_EDGES; e0 += nwarps * 8) {
        int s = 0, d = 0;
        float t = 2.f;
        if (lane < 8) {                        // one edge's geometry per lane
            s = __ldg(&src[e0 + lane]);
            d = __ldg(&dst[e0 + lane]);
            float ax = __ldg(&pos[s * 3 + 0]);
            float ay = __ldg(&pos[s * 3 + 1]);
            float az = __ldg(&pos[s * 3 + 2]);
            float bx = __ldg(&pos[d * 3 + 0]);
            float by = __ldg(&pos[d * 3 + 1]);
            float bz = __ldg(&pos[d * 3 + 2]);
            float dx = ax - bx, dy = ay - by, dz = az - bz;
            float r = sqrtf(dx * dx + dy * dy + dz * dz + 1e-12f);
            t = r * (1.f / CUTOFF);
            g_t[e0 + lane] = t;                // always written (deterministic)
        }
        int   sA = __shfl_sync(FULL, s, g);
        int   dA = __shfl_sync(FULL, d, g);
        int   sB = __shfl_sync(FULL, s, 4 + g);
        int   dB = __shfl_sync(FULL, d, 4 + g);
        float tA = __shfl_sync(FULL, t, g);
        float tB = __shfl_sync(FULL, t, 4 + g);
        bool fA = (tA < 1.f), fB = (tB < 1.f);

        float4 mA, mB;                 // both gather chains in flight before REDs
        if (fA) {
            float ft = tA * (float)TABK;
            int   i0 = (int)ft;
            float fr = ft - (float)i0;
            float4 a = tab1v[i0 * 8 + j];
            float4 b = tab1v[i0 * 8 + 8 + j];
            float4 xv = *reinterpret_cast<const float4*>(&g_x0[(size_t)sA * F + j * 4]);
            mA = make_float4(fmaf(fr, b.x - a.x, a.x) * xv.x,
                             fmaf(fr, b.y - a.y, a.y) * xv.y,
                             fmaf(fr, b.z - a.z, a.z) * xv.z,
                             fmaf(fr, b.w - a.w, a.w) * xv.w);
        }
        if (fB) {
            float ft = tB * (float)TABK;
            int   i0 = (int)ft;
            float fr = ft - (float)i0;
            float4 a = tab1v[i0 * 8 + j];
            float4 b = tab1v[i0 * 8 + 8 + j];
            float4 xv = *reinterpret_cast<const float4*>(&g_x0[(size_t)sB * F + j * 4]);
            mB = make_float4(fmaf(fr, b.x - a.x, a.x) * xv.x,
                             fmaf(fr, b.y - a.y, a.y) * xv.y,
                             fmaf(fr, b.z - a.z, a.z) * xv.z,
                             fmaf(fr, b.w - a.w, a.w) * xv.w);
        }
        if (fA) atomicAdd(reinterpret_cast<float4*>(&g_yacc[(size_t)dA * F + j * 4]), mA);
        if (fB) atomicAdd(reinterpret_cast<float4*>(&g_yacc[(size_t)dB * F + j * 4]), mB);
    }
}

// ---------------- K2: node update 1 — thread per node, f32x2 MACs ------------
__global__ void k_node1(const float* __restrict__ W1, const float* __restrict__ b1,
                        const float* __restrict__ W2, const float* __restrict__ b2,
                        const float* __restrict__ c0) {
    __shared__ ull W1s[F * F / 2];          // natural float2 pairs of row-major W
    __shared__ ull W2s[F * F / 2];
    __shared__ float bs[2 * F];
    for (int i = threadIdx.x; i < F * F / 2; i += blockDim.x) {
        W1s[i] = reinterpret_cast<const ull*>(W1)[i];
        W2s[i] = reinterpret_cast<const ull*>(W2)[i];
    }
    for (int i = threadIdx.x; i < F; i += blockDim.x) {
        bs[i]     = __ldg(&b1[i]);
        bs[F + i] = __ldg(&b2[i]);
    }
    __syncthreads();
    int n = blockIdx.x * blockDim.x + threadIdx.x;
    if (n >= N_NODES) return;
    float sc = siluf(__ldg(&c0[0]));

    float y[F];
    const float4* yv = reinterpret_cast<const float4*>(&g_yacc[(size_t)n * F]);
#pragma unroll
    for (int k = 0; k < 8; k++) {
        float4 v = yv[k];
        y[4 * k] = v.x; y[4 * k + 1] = v.y; y[4 * k + 2] = v.z; y[4 * k + 3] = v.w;
    }

    ull acc[F / 2];
#pragma unroll
    for (int gp = 0; gp < F / 2; gp++) acc[gp] = pk2(bs[2 * gp], bs[2 * gp + 1]);
#pragma unroll
    for (int f = 0; f < F; f++) {
        ull yf = pk2(y[f], y[f]);
#pragma unroll
        for (int gp = 0; gp < F / 2; gp++) fma2(acc[gp], yf, W1s[f * (F / 2) + gp]);
    }
    float gact[F];
#pragma unroll
    for (int gp = 0; gp < F / 2; gp++) upk2(acc[gp], gact[2 * gp], gact[2 * gp + 1]);
#pragma unroll
    for (int f = 0; f < F; f++) gact[f] = siluf(gact[f]);

#pragma unroll
    for (int gp = 0; gp < F / 2; gp++) acc[gp] = pk2(bs[F + 2 * gp], bs[F + 2 * gp + 1]);
#pragma unroll
    for (int f = 0; f < F; f++) {
        ull gf = pk2(gact[f], gact[f]);
#pragma unroll
        for (int gp = 0; gp < F / 2; gp++) fma2(acc[gp], gf, W2s[f * (F / 2) + gp]);
    }

    float4* x0v = reinterpret_cast<float4*>(&g_x0[(size_t)n * F]);
    float4* ya  = reinterpret_cast<float4*>(&g_yacc[(size_t)n * F]);
#pragma unroll
    for (int k = 0; k < 8; k++) {
        float a0, a1, a2, a3;
        upk2(acc[2 * k], a0, a1);
        upk2(acc[2 * k + 1], a2, a3);
        float4 xv = x0v[k];
        float4 xp = make_float4(fmaf(sc, a0, xv.x), fmaf(sc, a1, xv.y),
                                fmaf(sc, a2, xv.z), fmaf(sc, a3, xv.w));
        x0v[k] = xp;                  // x0' for pass 2
        ya[k]  = xp;                  // init accumulator for y0
    }
}

// ---------------- K3: edge pass 2 — 8 edges/warp, float4, p2 from table ------
__global__ void k_edge2(const int* __restrict__ src, const int* __restrict__ dst) {
    int lane   = threadIdx.x & 31;
    int g      = lane >> 3;
    int j      = lane & 7;
    int warp   = blockIdx.x * (blockDim.x >> 5) + (threadIdx.x >> 5);
    int nwarps = gridDim.x * (blockDim.x >> 5);
    const float4* tab2v = reinterpret_cast<const float4*>(g_tab2);

    for (int e0 = warp * 8; e0 < N_EDGES; e0 += nwarps * 8) {
        int sd = 0;
        float tl = 2.f;
        if (lane < 16) sd = __ldg(lane < 8 ? &src[e0 + lane] : &dst[e0 + (lane - 8)]);
        if (lane < 8)  tl = g_t[e0 + lane];
        int   sA = __shfl_sync(FULL, sd, g);
        int   dA = __shfl_sync(FULL, sd, 8 + g);
        int   sB = __shfl_sync(FULL, sd, 4 + g);
        int   dB = __shfl_sync(FULL, sd, 12 + g);
        float tA = __shfl_sync(FULL, tl, g);
        float tB = __shfl_sync(FULL, tl, 4 + g);
        bool fA = (tA < 1.f), fB = (tB < 1.f);

        float4 mA, mB;
        if (fA) {
            float ft = tA * (float)TABK;
            int   i0 = (int)ft;
            float fr = ft - (float)i0;
            float4 a = tab2v[i0 * 8 + j];
            float4 b = tab2v[i0 * 8 + 8 + j];
            float4 xv = *reinterpret_cast<const float4*>(&g_x0[(size_t)sA * F + j * 4]);
            mA = make_float4(fmaf(fr, b.x - a.x, a.x) * xv.x,
                             fmaf(fr, b.y - a.y, a.y) * xv.y,
                             fmaf(fr, b.z - a.z, a.z) * xv.z,
                             fmaf(fr, b.w - a.w, a.w) * xv.w);
        }
        if (fB) {
            float ft = tB * (float)TABK;
            int   i0 = (int)ft;
            float fr = ft - (float)i0;
            float4 a = tab2v[i0 * 8 + j];
            float4 b = tab2v[i0 * 8 + 8 + j];
            float4 xv = *reinterpret_cast<const float4*>(&g_x0[(size_t)sB * F + j * 4]);
            mB = make_float4(fmaf(fr, b.x - a.x, a.x) * xv.x,
                             fmaf(fr, b.y - a.y, a.y) * xv.y,
                             fmaf(fr, b.z - a.z, a.z) * xv.z,
                             fmaf(fr, b.w - a.w, a.w) * xv.w);
        }
        if (fA) atomicAdd(reinterpret_cast<float4*>(&g_yacc[(size_t)dA * F + j * 4]), mA);
        if (fB) atomicAdd(reinterpret_cast<float4*>(&g_yacc[(size_t)dB * F + j * 4]), mB);
    }
}

// ---------------- K4: node update 2 + readout — thread per node, f32x2 -------
__global__ void k_node2(const float* __restrict__ W11, const float* __restrict__ b11,
                        const float* __restrict__ W21, const float* __restrict__ b21,
                        const float* __restrict__ c1,
                        const float* __restrict__ Wro1, const float* __restrict__ bro1,
                        const float* __restrict__ Wro2, const float* __restrict__ bro2,
                        const float* __restrict__ abias, const int* __restrict__ z,
                        const int* __restrict__ bseg, float* __restrict__ out) {
    __shared__ ull W11s[F * F / 2];
    __shared__ ull W21s[F * F / 2];
    __shared__ ull Wro1s[F * F / 2];
    __shared__ float bs[3 * F];
    __shared__ float w2s[F];
    for (int i = threadIdx.x; i < F * F / 2; i += blockDim.x) {
        W11s[i]  = reinterpret_cast<const ull*>(W11)[i];
        W21s[i]  = reinterpret_cast<const ull*>(W21)[i];
        Wro1s[i] = reinterpret_cast<const ull*>(Wro1)[i];
    }
    for (int i = threadIdx.x; i < F; i += blockDim.x) {
        bs[i]         = __ldg(&b11[i]);
        bs[F + i]     = __ldg(&b21[i]);
        bs[2 * F + i] = __ldg(&bro1[i]);
        w2s[i]        = __ldg(&Wro2[i]);
    }
    __syncthreads();
    int n = blockIdx.x * blockDim.x + threadIdx.x;
    if (n >= N_NODES) return;
    float sc  = siluf(__ldg(&c1[0]));
    float br2 = __ldg(&bro2[0]);

    float y[F];
    const float4* yv = reinterpret_cast<const float4*>(&g_yacc[(size_t)n * F]);
#pragma unroll
    for (int k = 0; k < 8; k++) {
        float4 v = yv[k];
        y[4 * k] = v.x; y[4 * k + 1] = v.y; y[4 * k + 2] = v.z; y[4 * k + 3] = v.w;
    }

    // layer 1: a = silu(y0 @ W11 + b11)
    ull acc[F / 2];
#pragma unroll
    for (int gp = 0; gp < F / 2; gp++) acc[gp] = pk2(bs[2 * gp], bs[2 * gp + 1]);
#pragma unroll
    for (int f = 0; f < F; f++) {
        ull yf = pk2(y[f], y[f]);
#pragma unroll
        for (int gp = 0; gp < F / 2; gp++) fma2(acc[gp], yf, W11s[f * (F / 2) + gp]);
    }
    float a[F];
#pragma unroll
    for (int gp = 0; gp < F / 2; gp++) upk2(acc[gp], a[2 * gp], a[2 * gp + 1]);
#pragma unroll
    for (int f = 0; f < F; f++) a[f] = siluf(a[f]);

    // layer 2: yb = a @ W21 + b21 ; xs0 = x0' + sc*yb
#pragma unroll
    for (int gp = 0; gp < F / 2; gp++) acc[gp] = pk2(bs[F + 2 * gp], bs[F + 2 * gp + 1]);
#pragma unroll
    for (int f = 0; f < F; f++) {
        ull af = pk2(a[f], a[f]);
#pragma unroll
        for (int gp = 0; gp < F / 2; gp++) fma2(acc[gp], af, W21s[f * (F / 2) + gp]);
    }
    float xs0[F];
    const float4* x0v = reinterpret_cast<const float4*>(&g_x0[(size_t)n * F]);
#pragma unroll
    for (int k = 0; k < 8; k++) {
        float a0, a1, a2, a3;
        upk2(acc[2 * k], a0, a1);
        upk2(acc[2 * k + 1], a2, a3);
        float4 xv = x0v[k];
        xs0[4 * k]     = fmaf(sc, a0, xv.x);
        xs0[4 * k + 1] = fmaf(sc, a1, xv.y);
        xs0[4 * k + 2] = fmaf(sc, a2, xv.z);
        xs0[4 * k + 3] = fmaf(sc, a3, xv.w);
    }

    // readout: h = silu(xs0 @ Wro1 + bro1); e = h·Wro2 + bro2 + abias[z]
#pragma unroll
    for (int gp = 0; gp < F / 2; gp++) acc[gp] = pk2(bs[2 * F + 2 * gp], bs[2 * F + 2 * gp + 1]);
#pragma unroll
    for (int f = 0; f < F; f++) {
        ull xf = pk2(xs0[f], xs0[f]);
#pragma unroll
        for (int gp = 0; gp < F / 2; gp++) fma2(acc[gp], xf, Wro1s[f * (F / 2) + gp]);
    }
    float e = 0.f;
#pragma unroll
    for (int gp = 0; gp < F / 2; gp++) {
        float h0, h1;
        upk2(acc[gp], h0, h1);
        e = fmaf(siluf(h0), w2s[2 * gp], e);
        e = fmaf(siluf(h1), w2s[2 * gp + 1], e);
    }
    e += br2 + __ldg(&abias[z[n]]);
    atomicAdd(&out[bseg[n]], e);
}

// ---------------- launch ------------------------------------------------------
extern "C" void kernel_launch(void* const* d_in, const int* in_sizes, int n_in,
                              void* d_out, int out_size) {
    const float* positions  = (const float*)d_in[0];
    const float* embed      = (const float*)d_in[1];
    const float* Wy0        = (const float*)d_in[2];
    const float* Wx0        = (const float*)d_in[3];
    const float* W1_0       = (const float*)d_in[4];
    const float* b1_0       = (const float*)d_in[5];
    const float* W2_0       = (const float*)d_in[6];
    const float* b2_0       = (const float*)d_in[7];
    const float* c0         = (const float*)d_in[8];
    const float* Wr_last    = (const float*)d_in[9];
    const float* W1_1       = (const float*)d_in[10];
    const float* b1_1       = (const float*)d_in[11];
    const float* W2_1       = (const float*)d_in[12];
    const float* b2_1       = (const float*)d_in[13];
    const float* c1         = (const float*)d_in[14];
    const float* Wro1       = (const float*)d_in[15];
    const float* bro1       = (const float*)d_in[16];
    const float* Wro2       = (const float*)d_in[17];
    const float* bro2       = (const float*)d_in[18];
    const float* abias      = (const float*)d_in[19];
    const int*   z          = (const int*)d_in[20];
    const int*   dst_idx    = (const int*)d_in[21];
    const int*   src_idx    = (const int*)d_in[22];
    const int*   bseg       = (const int*)d_in[23];
    float*       out        = (float*)d_out;

    k_init<<<(N_NODES * F + 255) / 256, 256>>>(embed, z, out);
    k_tab<<<(TABK + 1 + 7) / 8, 256>>>(Wy0, Wx0, Wr_last);
    k_edge1<<<2048, 256>>>(positions, src_idx, dst_idx);
    k_node1<<<(N_NODES + 127) / 128, 128>>>(W1_0, b1_0, W2_0, b2_0, c0);
    k_edge2<<<2048, 256>>>(src_idx, dst_idx);
    k_node2<<<(N_NODES + 127) / 128, 128>>>(W1_1, b1_1, W2_1, b2_1, c1,
                                            Wro1, bro1, Wro2, bro2, abias, z, bseg, out);
}

// round 17
// speedup vs baseline: 2.6823x; 1.0230x over previous
#include <cuda_runtime.h>
#include <cuda_fp16.h>
#include <math.h>

#define N_NODES 50000
#define N_EDGES 400000
#define N_GRAPHS 512
#define F 32
#define NB 32
#define CUTOFF 5.0f
#define FULL 0xffffffffu
#define TABK 4096                     // knots over t in [0,1]

// ---------------- device scratch (no allocations allowed) ----------------
__device__ float g_x0[N_NODES * F];              // x0, later x0'
__device__ float g_yacc[N_NODES * F];            // segment-sum accumulator
__device__ float g_t[N_EDGES];                   // per-edge t = r/cutoff (all edges)
__device__ float g_tab1[(TABK + 1) * F];         // p1(t) table
__device__ float g_tab2[(TABK + 1) * F];         // p2(t) table

__device__ __forceinline__ float siluf(float x) { return x * (1.f / (1.f + __expf(-x))); }

typedef unsigned long long ull;
__device__ __forceinline__ ull pk2(float a, float b) {
    ull r; asm("mov.b64 %0, {%1, %2};" : "=l"(r) : "f"(a), "f"(b)); return r;
}
__device__ __forceinline__ void upk2(ull v, float& a, float& b) {
    asm("mov.b64 {%0, %1}, %2;" : "=f"(a), "=f"(b) : "l"(v));
}
__device__ __forceinline__ void fma2(ull& acc, ull a, ull b) {
    asm("fma.rn.f32x2 %0, %1, %2, %0;" : "+l"(acc) : "l"(a), "l"(b));
}

// ---------------- K0: x0 = embed[z], yacc = x0, zero d_out -------------------
__global__ void k_init(const float* __restrict__ embed, const int* __restrict__ z,
                       float* __restrict__ out) {
    int i = blockIdx.x * blockDim.x + threadIdx.x;
    if (i < N_GRAPHS) out[i] = 0.f;
    if (i < N_NODES * F) {
        int n = i >> 5, f = i & 31;
        float v = embed[z[n] * F + f];
        g_x0[i] = v;
        g_yacc[i] = v;
    }
}

// ---------------- KT: build p1/p2 tables (warp per knot) ---------------------
__global__ void k_tab(const float* __restrict__ Wy0, const float* __restrict__ Wx0,
                      const float* __restrict__ Wr) {
    __shared__ float2 ws2[NB][F];
    for (int i = threadIdx.x; i < NB * F; i += blockDim.x) {
        int b = i >> 5, f = i & 31;
        ws2[b][f] = make_float2(__ldg(&Wy0[i]) + __ldg(&Wx0[i]), __ldg(&Wr[i]));
    }
    __syncthreads();
    int lane = threadIdx.x & 31;
    int k    = blockIdx.x * (blockDim.x >> 5) + (threadIdx.x >> 5);
    if (k > TABK) return;

    float t = (float)k * (1.f / (float)TABK);
    float rbf = 0.f;
    if (t < 1.f) {
        float r = t * CUTOFF;
        float lb = lgammaf((float)NB) - lgammaf((float)lane + 1.f)
                 - lgammaf((float)NB - (float)lane);
        float kf = (float)lane;
        float fc = __expf(1.f - __fdividef(1.f, fmaxf(1.f - t * t, 1e-7f)));
        float u = __fdividef(r, r + 1.f);
        u = fminf(fmaxf(u, 1e-7f), 1.f - 1e-7f);
        rbf = __expf(lb + kf * __logf(u) + ((float)NB - 1.f - kf) * __logf(1.f - u)) * fc;
    }
    float p1 = 0.f, p2 = 0.f;
#pragma unroll
    for (int b = 0; b < NB; b++) {
        float rb = __shfl_sync(FULL, rbf, b);
        float2 w = ws2[b][lane];
        p1 = fmaf(rb, w.x, p1);
        p2 = fmaf(rb, w.y, p2);
    }
    g_tab1[k * F + lane] = p1;
    g_tab2[k * F + lane] = p2;
}

// ---------------- K1: edge pass 1 — 8 edges/warp, geometry on lanes 0..7 -----
__global__ void k_edge1(const float* __restrict__ pos,
                        const int* __restrict__ src, const int* __restrict__ dst) {
    int lane   = threadIdx.x & 31;
    int g      = lane >> 3;          // edge subgroup 0..3
    int j      = lane & 7;           // feature group (4 floats each)
    int warp   = blockIdx.x * (blockDim.x >> 5) + (threadIdx.x >> 5);
    int nwarps = gridDim.x * (blockDim.x >> 5);
    const float4* tab1v = reinterpret_cast<const float4*>(g_tab1);

    for (int e0 = warp * 8; e0 < N_EDGES; e0 += nwarps * 8) {
        int s = 0, d = 0;
        float t = 2.f;
        if (lane < 8) {                        // one edge's geometry per lane
            s = __ldg(&src[e0 + lane]);
            d = __ldg(&dst[e0 + lane]);
            float ax = __ldg(&pos[s * 3 + 0]);
            float ay = __ldg(&pos[s * 3 + 1]);
            float az = __ldg(&pos[s * 3 + 2]);
            float bx = __ldg(&pos[d * 3 + 0]);
            float by = __ldg(&pos[d * 3 + 1]);
            float bz = __ldg(&pos[d * 3 + 2]);
            float dx = ax - bx, dy = ay - by, dz = az - bz;
            float r = sqrtf(dx * dx + dy * dy + dz * dz + 1e-12f);
            t = r * (1.f / CUTOFF);
            g_t[e0 + lane] = t;                // always written (deterministic)
        }
        int   sA = __shfl_sync(FULL, s, g);
        int   dA = __shfl_sync(FULL, d, g);
        int   sB = __shfl_sync(FULL, s, 4 + g);
        int   dB = __shfl_sync(FULL, d, 4 + g);
        float tA = __shfl_sync(FULL, t, g);
        float tB = __shfl_sync(FULL, t, 4 + g);
        bool fA = (tA < 1.f), fB = (tB < 1.f);

        float4 mA, mB;                 // both gather chains in flight before REDs
        if (fA) {
            float ft = tA * (float)TABK;
            int   i0 = (int)ft;
            float fr = ft - (float)i0;
            float4 a = tab1v[i0 * 8 + j];
            float4 b = tab1v[i0 * 8 + 8 + j];
            float4 xv = *reinterpret_cast<const float4*>(&g_x0[(size_t)sA * F + j * 4]);
            mA = make_float4(fmaf(fr, b.x - a.x, a.x) * xv.x,
                             fmaf(fr, b.y - a.y, a.y) * xv.y,
                             fmaf(fr, b.z - a.z, a.z) * xv.z,
                             fmaf(fr, b.w - a.w, a.w) * xv.w);
        }
        if (fB) {
            float ft = tB * (float)TABK;
            int   i0 = (int)ft;
            float fr = ft - (float)i0;
            float4 a = tab1v[i0 * 8 + j];
            float4 b = tab1v[i0 * 8 + 8 + j];
            float4 xv = *reinterpret_cast<const float4*>(&g_x0[(size_t)sB * F + j * 4]);
            mB = make_float4(fmaf(fr, b.x - a.x, a.x) * xv.x,
                             fmaf(fr, b.y - a.y, a.y) * xv.y,
                             fmaf(fr, b.z - a.z, a.z) * xv.z,
                             fmaf(fr, b.w - a.w, a.w) * xv.w);
        }
        if (fA) atomicAdd(reinterpret_cast<float4*>(&g_yacc[(size_t)dA * F + j * 4]), mA);
        if (fB) atomicAdd(reinterpret_cast<float4*>(&g_yacc[(size_t)dB * F + j * 4]), mB);
    }
}

// ---------------- K2: node update 1 — 2 threads/node, f32x2, LDS.128 ---------
// Thread t in {0,1} computes outputs [16t, 16t+16); halves exchanged via shfl.
__global__ void k_node1(const float* __restrict__ W1, const float* __restrict__ b1,
                        const float* __restrict__ W2, const float* __restrict__ b2,
                        const float* __restrict__ c0) {
    __shared__ ulonglong2 W1s[F * F / 4];   // row f = 8 ulonglong2 (32 floats)
    __shared__ ulonglong2 W2s[F * F / 4];
    __shared__ float bs[2 * F];
    for (int i = threadIdx.x; i < F * F / 4; i += blockDim.x) {
        W1s[i] = reinterpret_cast<const ulonglong2*>(W1)[i];
        W2s[i] = reinterpret_cast<const ulonglong2*>(W2)[i];
    }
    for (int i = threadIdx.x; i < F; i += blockDim.x) {
        bs[i]     = __ldg(&b1[i]);
        bs[F + i] = __ldg(&b2[i]);
    }
    __syncthreads();
    int tid = blockIdx.x * blockDim.x + threadIdx.x;
    int n = tid >> 1;
    int t = tid & 1;
    if (n >= N_NODES) return;
    float sc = siluf(__ldg(&c0[0]));
    int h0off = 16 * t, h1off = 16 - 16 * t;    // own / partner half offsets

    float y[F];
    const float4* yv = reinterpret_cast<const float4*>(&g_yacc[(size_t)n * F]);
#pragma unroll
    for (int k = 0; k < 8; k++) {
        float4 v = yv[k];
        y[4 * k] = v.x; y[4 * k + 1] = v.y; y[4 * k + 2] = v.z; y[4 * k + 3] = v.w;
    }

    // layer 1: own 16 outputs
    ull acc[8];
#pragma unroll
    for (int q = 0; q < 8; q++) acc[q] = pk2(bs[h0off + 2 * q], bs[h0off + 2 * q + 1]);
#pragma unroll
    for (int f = 0; f < F; f++) {
        ull yf = pk2(y[f], y[f]);
#pragma unroll
        for (int q = 0; q < 4; q++) {
            ulonglong2 w = W1s[f * 8 + 4 * t + q];
            fma2(acc[2 * q],     yf, w.x);
            fma2(acc[2 * q + 1], yf, w.y);
        }
    }
    float a[F];
#pragma unroll
    for (int q = 0; q < 8; q++) {
        float u0, u1; upk2(acc[q], u0, u1);
        a[h0off + 2 * q]     = siluf(u0);
        a[h0off + 2 * q + 1] = siluf(u1);
    }
#pragma unroll
    for (int q = 0; q < 8; q++) {               // exchange halves with partner lane
        ull own = pk2(a[h0off + 2 * q], a[h0off + 2 * q + 1]);
        ull par = __shfl_xor_sync(FULL, own, 1);
        upk2(par, a[h1off + 2 * q], a[h1off + 2 * q + 1]);
    }

    // layer 2: own 16 outputs
#pragma unroll
    for (int q = 0; q < 8; q++) acc[q] = pk2(bs[F + h0off + 2 * q], bs[F + h0off + 2 * q + 1]);
#pragma unroll
    for (int f = 0; f < F; f++) {
        ull af = pk2(a[f], a[f]);
#pragma unroll
        for (int q = 0; q < 4; q++) {
            ulonglong2 w = W2s[f * 8 + 4 * t + q];
            fma2(acc[2 * q],     af, w.x);
            fma2(acc[2 * q + 1], af, w.y);
        }
    }

    float4* x0v = reinterpret_cast<float4*>(&g_x0[(size_t)n * F + h0off]);
    float4* ya  = reinterpret_cast<float4*>(&g_yacc[(size_t)n * F + h0off]);
#pragma unroll
    for (int k = 0; k < 4; k++) {
        float a0, a1, a2, a3;
        upk2(acc[2 * k], a0, a1);
        upk2(acc[2 * k + 1], a2, a3);
        float4 xv = x0v[k];
        float4 xp = make_float4(fmaf(sc, a0, xv.x), fmaf(sc, a1, xv.y),
                                fmaf(sc, a2, xv.z), fmaf(sc, a3, xv.w));
        x0v[k] = xp;                  // x0' for pass 2
        ya[k]  = xp;                  // init accumulator for y0
    }
}

// ---------------- K3: edge pass 2 — 8 edges/warp, float4, p2 from table ------
__global__ void k_edge2(const int* __restrict__ src, const int* __restrict__ dst) {
    int lane   = threadIdx.x & 31;
    int g      = lane >> 3;
    int j      = lane & 7;
    int warp   = blockIdx.x * (blockDim.x >> 5) + (threadIdx.x >> 5);
    int nwarps = gridDim.x * (blockDim.x >> 5);
    const float4* tab2v = reinterpret_cast<const float4*>(g_tab2);

    for (int e0 = warp * 8; e0 < N_EDGES; e0 += nwarps * 8) {
        int sd = 0;
        float tl = 2.f;
        if (lane < 16) sd = __ldg(lane < 8 ? &src[e0 + lane] : &dst[e0 + (lane - 8)]);
        if (lane < 8)  tl = g_t[e0 + lane];
        int   sA = __shfl_sync(FULL, sd, g);
        int   dA = __shfl_sync(FULL, sd, 8 + g);
        int   sB = __shfl_sync(FULL, sd, 4 + g);
        int   dB = __shfl_sync(FULL, sd, 12 + g);
        float tA = __shfl_sync(FULL, tl, g);
        float tB = __shfl_sync(FULL, tl, 4 + g);
        bool fA = (tA < 1.f), fB = (tB < 1.f);

        float4 mA, mB;
        if (fA) {
            float ft = tA * (float)TABK;
            int   i0 = (int)ft;
            float fr = ft - (float)i0;
            float4 a = tab2v[i0 * 8 + j];
            float4 b = tab2v[i0 * 8 + 8 + j];
            float4 xv = *reinterpret_cast<const float4*>(&g_x0[(size_t)sA * F + j * 4]);
            mA = make_float4(fmaf(fr, b.x - a.x, a.x) * xv.x,
                             fmaf(fr, b.y - a.y, a.y) * xv.y,
                             fmaf(fr, b.z - a.z, a.z) * xv.z,
                             fmaf(fr, b.w - a.w, a.w) * xv.w);
        }
        if (fB) {
            float ft = tB * (float)TABK;
            int   i0 = (int)ft;
            float fr = ft - (float)i0;
            float4 a = tab2v[i0 * 8 + j];
            float4 b = tab2v[i0 * 8 + 8 + j];
            float4 xv = *reinterpret_cast<const float4*>(&g_x0[(size_t)sB * F + j * 4]);
            mB = make_float4(fmaf(fr, b.x - a.x, a.x) * xv.x,
                             fmaf(fr, b.y - a.y, a.y) * xv.y,
                             fmaf(fr, b.z - a.z, a.z) * xv.z,
                             fmaf(fr, b.w - a.w, a.w) * xv.w);
        }
        if (fA) atomicAdd(reinterpret_cast<float4*>(&g_yacc[(size_t)dA * F + j * 4]), mA);
        if (fB) atomicAdd(reinterpret_cast<float4*>(&g_yacc[(size_t)dB * F + j * 4]), mB);
    }
}

// ---------------- K4: node update 2 + readout — 2 threads/node, f32x2 --------
__global__ void k_node2(const float* __restrict__ W11, const float* __restrict__ b11,
                        const float* __restrict__ W21, const float* __restrict__ b21,
                        const float* __restrict__ c1,
                        const float* __restrict__ Wro1, const float* __restrict__ bro1,
                        const float* __restrict__ Wro2, const float* __restrict__ bro2,
                        const float* __restrict__ abias, const int* __restrict__ z,
                        const int* __restrict__ bseg, float* __restrict__ out) {
    __shared__ ulonglong2 W11s[F * F / 4];
    __shared__ ulonglong2 W21s[F * F / 4];
    __shared__ ulonglong2 Wro1s[F * F / 4];
    __shared__ float bs[3 * F];
    __shared__ float w2s[F];
    for (int i = threadIdx.x; i < F * F / 4; i += blockDim.x) {
        W11s[i]  = reinterpret_cast<const ulonglong2*>(W11)[i];
        W21s[i]  = reinterpret_cast<const ulonglong2*>(W21)[i];
        Wro1s[i] = reinterpret_cast<const ulonglong2*>(Wro1)[i];
    }
    for (int i = threadIdx.x; i < F; i += blockDim.x) {
        bs[i]         = __ldg(&b11[i]);
        bs[F + i]     = __ldg(&b21[i]);
        bs[2 * F + i] = __ldg(&bro1[i]);
        w2s[i]        = __ldg(&Wro2[i]);
    }
    __syncthreads();
    int tid = blockIdx.x * blockDim.x + threadIdx.x;
    int n = tid >> 1;
    int t = tid & 1;
    if (n >= N_NODES) return;
    float sc  = siluf(__ldg(&c1[0]));
    float br2 = __ldg(&bro2[0]);
    int h0off = 16 * t, h1off = 16 - 16 * t;

    float y[F];
    const float4* yv = reinterpret_cast<const float4*>(&g_yacc[(size_t)n * F]);
#pragma unroll
    for (int k = 0; k < 8; k++) {
        float4 v = yv[k];
        y[4 * k] = v.x; y[4 * k + 1] = v.y; y[4 * k + 2] = v.z; y[4 * k + 3] = v.w;
    }

    // layer 1
    ull acc[8];
#pragma unroll
    for (int q = 0; q < 8; q++) acc[q] = pk2(bs[h0off + 2 * q], bs[h0off + 2 * q + 1]);
#pragma unroll
    for (int f = 0; f < F; f++) {
        ull yf = pk2(y[f], y[f]);
#pragma unroll
        for (int q = 0; q < 4; q++) {
            ulonglong2 w = W11s[f * 8 + 4 * t + q];
            fma2(acc[2 * q],     yf, w.x);
            fma2(acc[2 * q + 1], yf, w.y);
        }
    }
    float a[F];
#pragma unroll
    for (int q = 0; q < 8; q++) {
        float u0, u1; upk2(acc[q], u0, u1);
        a[h0off + 2 * q]     = siluf(u0);
        a[h0off + 2 * q + 1] = siluf(u1);
    }
#pragma unroll
    for (int q = 0; q < 8; q++) {
        ull own = pk2(a[h0off + 2 * q], a[h0off + 2 * q + 1]);
        ull par = __shfl_xor_sync(FULL, own, 1);
        upk2(par, a[h1off + 2 * q], a[h1off + 2 * q + 1]);
    }

    // layer 2 + residual -> xs0 (own half), then exchange
#pragma unroll
    for (int q = 0; q < 8; q++) acc[q] = pk2(bs[F + h0off + 2 * q], bs[F + h0off + 2 * q + 1]);
#pragma unroll
    for (int f = 0; f < F; f++) {
        ull af = pk2(a[f], a[f]);
#pragma unroll
        for (int q = 0; q < 4; q++) {
            ulonglong2 w = W21s[f * 8 + 4 * t + q];
            fma2(acc[2 * q],     af, w.x);
            fma2(acc[2 * q + 1], af, w.y);
        }
    }
    float xs0[F];
    const float4* x0v = reinterpret_cast<const float4*>(&g_x0[(size_t)n * F + h0off]);
#pragma unroll
    for (int k = 0; k < 4; k++) {
        float a0, a1, a2, a3;
        upk2(acc[2 * k], a0, a1);
        upk2(acc[2 * k + 1], a2, a3);
        float4 xv = x0v[k];
        xs0[h0off + 4 * k]     = fmaf(sc, a0, xv.x);
        xs0[h0off + 4 * k + 1] = fmaf(sc, a1, xv.y);
        xs0[h0off + 4 * k + 2] = fmaf(sc, a2, xv.z);
        xs0[h0off + 4 * k + 3] = fmaf(sc, a3, xv.w);
    }
#pragma unroll
    for (int q = 0; q < 8; q++) {
        ull own = pk2(xs0[h0off + 2 * q], xs0[h0off + 2 * q + 1]);
        ull par = __shfl_xor_sync(FULL, own, 1);
        upk2(par, xs0[h1off + 2 * q], xs0[h1off + 2 * q + 1]);
    }

    // readout layer (own 16 h) + dot with Wro2
#pragma unroll
    for (int q = 0; q < 8; q++) acc[q] = pk2(bs[2 * F + h0off + 2 * q], bs[2 * F + h0off + 2 * q + 1]);
#pragma unroll
    for (int f = 0; f < F; f++) {
        ull xf = pk2(xs0[f], xs0[f]);
#pragma unroll
        for (int q = 0; q < 4; q++) {
            ulonglong2 w = Wro1s[f * 8 + 4 * t + q];
            fma2(acc[2 * q],     xf, w.x);
            fma2(acc[2 * q + 1], xf, w.y);
        }
    }
    float e = 0.f;
#pragma unroll
    for (int q = 0; q < 8; q++) {
        float u0, u1; upk2(acc[q], u0, u1);
        e = fmaf(siluf(u0), w2s[h0off + 2 * q], e);
        e = fmaf(siluf(u1), w2s[h0off + 2 * q + 1], e);
    }
    e += __shfl_xor_sync(FULL, e, 1);            // partner half
    if (t == 0) {
        e += br2 + __ldg(&abias[z[n]]);
        atomicAdd(&out[bseg[n]], e);
    }
}

// ---------------- launch ------------------------------------------------------
extern "C" void kernel_launch(void* const* d_in, const int* in_sizes, int n_in,
                              void* d_out, int out_size) {
    const float* positions  = (const float*)d_in[0];
    const float* embed      = (const float*)d_in[1];
    const float* Wy0        = (const float*)d_in[2];
    const float* Wx0        = (const float*)d_in[3];
    const float* W1_0       = (const float*)d_in[4];
    const float* b1_0       = (const float*)d_in[5];
    const float* W2_0       = (const float*)d_in[6];
    const float* b2_0       = (const float*)d_in[7];
    const float* c0         = (const float*)d_in[8];
    const float* Wr_last    = (const float*)d_in[9];
    const float* W1_1       = (const float*)d_in[10];
    const float* b1_1       = (const float*)d_in[11];
    const float* W2_1       = (const float*)d_in[12];
    const float* b2_1       = (const float*)d_in[13];
    const float* c1         = (const float*)d_in[14];
    const float* Wro1       = (const float*)d_in[15];
    const float* bro1       = (const float*)d_in[16];
    const float* Wro2       = (const float*)d_in[17];
    const float* bro2       = (const float*)d_in[18];
    const float* abias      = (const float*)d_in[19];
    const int*   z          = (const int*)d_in[20];
    const int*   dst_idx    = (const int*)d_in[21];
    const int*   src_idx    = (const int*)d_in[22];
    const int*   bseg       = (const int*)d_in[23];
    float*       out        = (float*)d_out;

    k_init<<<(N_NODES * F + 255) / 256, 256>>>(embed, z, out);
    k_tab<<<(TABK + 1 + 7) / 8, 256>>>(Wy0, Wx0, Wr_last);
    k_edge1<<<2048, 256>>>(positions, src_idx, dst_idx);
    k_node1<<<(2 * N_NODES + 127) / 128, 128>>>(W1_0, b1_0, W2_0, b2_0, c0);
    k_edge2<<<2048, 256>>>(src_idx, dst_idx);
    k_node2<<<(2 * N_NODES + 127) / 128, 128>>>(W1_1, b1_1, W2_1, b2_1, c1,
                                                Wro1, bro1, Wro2, bro2, abias, z, bseg, out);
}